// round 2
// baseline (speedup 1.0000x reference)
#include <cuda_runtime.h>
#include <cuda_bf16.h>
#include <cstdint>

#define H 65536
#define C 384
#define S 1024

// scratch (allocation-free rule: device globals)
__device__ float d_num[S * C];
__device__ float d_den[S * C];
__device__ float d_z[S * C];
__device__ int   d_is64;

__device__ __forceinline__ uint32_t f2tf32(float f) {
    uint32_t r;
    asm("cvt.rna.tf32.f32 %0, %1;" : "=r"(r) : "f"(f));
    return r;
}

__device__ __forceinline__ void mma8(float& c0, float& c1, float& c2, float& c3,
                                     uint32_t a0, uint32_t a1, uint32_t a2, uint32_t a3,
                                     uint32_t b0, uint32_t b1) {
    asm volatile(
        "mma.sync.aligned.m16n8k8.row.col.f32.tf32.tf32.f32 "
        "{%0,%1,%2,%3}, {%4,%5,%6,%7}, {%8,%9}, {%0,%1,%2,%3};\n"
        : "+f"(c0), "+f"(c1), "+f"(c2), "+f"(c3)
        : "r"(a0), "r"(a1), "r"(a2), "r"(a3), "r"(b0), "r"(b1));
}

__device__ __forceinline__ void red2(float* p, float a, float b) {
    asm volatile("red.global.add.v2.f32 [%0], {%1,%2};" :: "l"(p), "f"(a), "f"(b) : "memory");
}

__device__ __forceinline__ float clamp50(float v) {
    return fminf(fmaxf(v, -50.0f), 50.0f);
}

// read segment id under either dtype interpretation, clamped to valid range
__device__ __forceinline__ int seg_at(const void* ix, int i, int is64) {
    int v = is64 ? (int)((const long long*)ix)[i] : ((const int*)ix)[i];
    return min(max(v, 0), S - 1);
}

// ---------------------------------------------------------------------------
// Kernel -1: detect ix dtype. Reads only the first 32768 int64 slots, which
// fits inside the buffer whether ix is int32 (256KB) or int64 (512KB).
// int32 data reinterpreted as int64 gives values >= 2^32 w.h.p.
// ---------------------------------------------------------------------------
__global__ void detect_kernel(const void* ix) {
    __shared__ int bad;
    if (threadIdx.x == 0) bad = 0;
    __syncthreads();
    const long long* p = (const long long*)ix;
    int local = 0;
    for (int i = threadIdx.x; i < 32768; i += blockDim.x) {
        long long v = p[i];
        if (v < 0 || v >= S) local = 1;
    }
    if (local) bad = 1;
    __syncthreads();
    if (threadIdx.x == 0) d_is64 = bad ? 0 : 1;
}

// ---------------------------------------------------------------------------
// Kernel 0: zero num/den
// ---------------------------------------------------------------------------
__global__ void zero_kernel() {
    int i = blockIdx.x * blockDim.x + threadIdx.x;
    if (i < S * C) { d_num[i] = 0.0f; d_den[i] = 0.0f; }
}

// ---------------------------------------------------------------------------
// Kernel 1: fused  fx = x@f_w^T, gx = x@g_w^T  +  exp  +  segment reductions
// CTA: 128 rows of x, full K=384 in smem (tf32). 6 column-pair iterations;
// f-cols and g-cols computed simultaneously so (fx, w) meet in registers,
// then red.add v2 into num/den.
// 256 threads = 8 warps, warp grid 4(M) x 2(N): warp tile 32(M) x 32(N).
// ---------------------------------------------------------------------------
#define BM 128
#define XSTR 388   // 384 + 4 pad
#define WSTR 36    // 32 + 4 pad

#define XS_WORDS   (BM * XSTR)            // 49664
#define WF_OFF     XS_WORDS
#define WG_OFF     (WF_OFF + 64 * WSTR)
#define SEG_OFF    (WG_OFF + 64 * WSTR)
#define SMEM_MAIN  ((SEG_OFF + BM) * 4)   // 217600 bytes

__global__ __launch_bounds__(256, 1) void fused_fg_kernel(
    const float* __restrict__ x, const void* __restrict__ ix,
    const float* __restrict__ f_w, const float* __restrict__ f_b,
    const float* __restrict__ g_w, const float* __restrict__ g_b) {
    extern __shared__ uint32_t sm[];
    uint32_t* xs  = sm;
    uint32_t* wfs = sm + WF_OFF;
    uint32_t* wgs = sm + WG_OFF;
    int*      segs = (int*)(sm + SEG_OFF);

    const int tid = threadIdx.x;
    const int lane = tid & 31;
    const int warp = tid >> 5;
    const int wm = warp >> 1;   // 0..3
    const int wn = warp & 1;    // 0..1
    const int q = lane & 3;     // 0..3
    const int p = lane >> 2;    // 0..7
    const int blockRow = blockIdx.x * BM;

    const int is64 = d_is64;
    if (tid < BM) segs[tid] = seg_at(ix, blockRow + tid, is64);

    // load x tile [128 x 384] -> tf32 smem
    for (int i = tid; i < BM * (C / 4); i += 256) {
        int r = i / (C / 4), c4 = i % (C / 4);
        float4 v = *(const float4*)(x + (size_t)(blockRow + r) * C + c4 * 4);
        uint32_t* dst = xs + r * XSTR + c4 * 4;
        dst[0] = f2tf32(v.x); dst[1] = f2tf32(v.y);
        dst[2] = f2tf32(v.z); dst[3] = f2tf32(v.w);
    }

    const int n0 = tid >> 3;        // 0..31
    const int k4 = (tid & 7) * 4;   // 0,4,..,28

    for (int np = 0; np < 6; ++np) {
        float accf[2][4][4];
        float accg[2][4][4];
        #pragma unroll
        for (int a = 0; a < 2; a++)
            #pragma unroll
            for (int b = 0; b < 4; b++)
                #pragma unroll
                for (int c = 0; c < 4; c++) { accf[a][b][c] = 0.0f; accg[a][b][c] = 0.0f; }

        const float* fW = f_w + (size_t)(np * 64) * C;
        const float* gW = g_w + (size_t)(np * 64) * C;

        // register prefetch of weight chunk 0
        float4 rf0 = *(const float4*)(fW + (size_t)n0 * C + k4);
        float4 rf1 = *(const float4*)(fW + (size_t)(n0 + 32) * C + k4);
        float4 rg0 = *(const float4*)(gW + (size_t)n0 * C + k4);
        float4 rg1 = *(const float4*)(gW + (size_t)(n0 + 32) * C + k4);

        for (int kc = 0; kc < 12; ++kc) {
            __syncthreads();  // previous chunk fully consumed (and xs/segs ready)
            {
                uint32_t* d0 = wfs + n0 * WSTR + k4;
                d0[0] = f2tf32(rf0.x); d0[1] = f2tf32(rf0.y); d0[2] = f2tf32(rf0.z); d0[3] = f2tf32(rf0.w);
                uint32_t* d1 = wfs + (n0 + 32) * WSTR + k4;
                d1[0] = f2tf32(rf1.x); d1[1] = f2tf32(rf1.y); d1[2] = f2tf32(rf1.z); d1[3] = f2tf32(rf1.w);
                uint32_t* e0 = wgs + n0 * WSTR + k4;
                e0[0] = f2tf32(rg0.x); e0[1] = f2tf32(rg0.y); e0[2] = f2tf32(rg0.z); e0[3] = f2tf32(rg0.w);
                uint32_t* e1 = wgs + (n0 + 32) * WSTR + k4;
                e1[0] = f2tf32(rg1.x); e1[1] = f2tf32(rg1.y); e1[2] = f2tf32(rg1.z); e1[3] = f2tf32(rg1.w);
            }
            __syncthreads();
            if (kc + 1 < 12) {  // prefetch next chunk while computing
                int ko = (kc + 1) * 32 + k4;
                rf0 = *(const float4*)(fW + (size_t)n0 * C + ko);
                rf1 = *(const float4*)(fW + (size_t)(n0 + 32) * C + ko);
                rg0 = *(const float4*)(gW + (size_t)n0 * C + ko);
                rg1 = *(const float4*)(gW + (size_t)(n0 + 32) * C + ko);
            }
            #pragma unroll
            for (int kk = 0; kk < 4; ++kk) {
                const int krow = kc * 32 + kk * 8;
                uint32_t a[2][4];
                #pragma unroll
                for (int mt = 0; mt < 2; ++mt) {
                    int r0 = wm * 32 + mt * 16 + p;
                    a[mt][0] = xs[r0 * XSTR + krow + q];
                    a[mt][1] = xs[(r0 + 8) * XSTR + krow + q];
                    a[mt][2] = xs[r0 * XSTR + krow + q + 4];
                    a[mt][3] = xs[(r0 + 8) * XSTR + krow + q + 4];
                }
                #pragma unroll
                for (int nt = 0; nt < 4; ++nt) {
                    int nb = wn * 32 + nt * 8 + p;
                    uint32_t bf0 = wfs[nb * WSTR + kk * 8 + q];
                    uint32_t bf1 = wfs[nb * WSTR + kk * 8 + q + 4];
                    uint32_t bg0 = wgs[nb * WSTR + kk * 8 + q];
                    uint32_t bg1 = wgs[nb * WSTR + kk * 8 + q + 4];
                    #pragma unroll
                    for (int mt = 0; mt < 2; ++mt) {
                        mma8(accf[mt][nt][0], accf[mt][nt][1], accf[mt][nt][2], accf[mt][nt][3],
                             a[mt][0], a[mt][1], a[mt][2], a[mt][3], bf0, bf1);
                        mma8(accg[mt][nt][0], accg[mt][nt][1], accg[mt][nt][2], accg[mt][nt][3],
                             a[mt][0], a[mt][1], a[mt][2], a[mt][3], bg0, bg1);
                    }
                }
            }
        }

        // epilogue: w = exp(clip(gx+gb)), p = (fx+fb)*w, red into segments
        #pragma unroll
        for (int mt = 0; mt < 2; ++mt) {
            int rloc = wm * 32 + mt * 16 + p;
            int s0 = segs[rloc];
            int s1 = segs[rloc + 8];
            #pragma unroll
            for (int nt = 0; nt < 4; ++nt) {
                int col = np * 64 + wn * 32 + nt * 8 + q * 2;
                float fb0 = __ldg(f_b + col), fb1 = __ldg(f_b + col + 1);
                float gb0 = __ldg(g_b + col), gb1 = __ldg(g_b + col + 1);
                float w00 = __expf(clamp50(accg[mt][nt][0] + gb0));
                float w01 = __expf(clamp50(accg[mt][nt][1] + gb1));
                float w10 = __expf(clamp50(accg[mt][nt][2] + gb0));
                float w11 = __expf(clamp50(accg[mt][nt][3] + gb1));
                float p00 = (accf[mt][nt][0] + fb0) * w00;
                float p01 = (accf[mt][nt][1] + fb1) * w01;
                float p10 = (accf[mt][nt][2] + fb0) * w10;
                float p11 = (accf[mt][nt][3] + fb1) * w11;
                red2(d_num + (size_t)s0 * C + col, p00, p01);
                red2(d_den + (size_t)s0 * C + col, w00, w01);
                red2(d_num + (size_t)s1 * C + col, p10, p11);
                red2(d_den + (size_t)s1 * C + col, w10, w11);
            }
        }
    }
}

// ---------------------------------------------------------------------------
// Kernel 2: z = (num/max(den,1e-9)) @ h_w^T + h_b   over 1024 segment rows
// CTA: 32 seg rows x full N=384. 8 warps: grid 2(M) x 4(N), warp 16 x 96.
// ---------------------------------------------------------------------------
#define HBM 32
#define AS_WORDS (HBM * XSTR)                 // 12416
#define WH_OFF   AS_WORDS
#define SMEM_H   ((WH_OFF + 384 * WSTR) * 4)  // 104960 bytes

__global__ __launch_bounds__(256, 1) void hgemm_kernel(
    const float* __restrict__ h_w, const float* __restrict__ h_b) {
    extern __shared__ uint32_t sm[];
    uint32_t* as_ = sm;
    uint32_t* whs = sm + WH_OFF;

    const int tid = threadIdx.x;
    const int lane = tid & 31;
    const int warp = tid >> 5;
    const int wm = warp >> 2;   // 0..1
    const int wn = warp & 3;    // 0..3
    const int q = lane & 3;
    const int p = lane >> 2;
    const int blockRow = blockIdx.x * HBM;

    // load ratio tile
    for (int i = tid; i < HBM * (C / 4); i += 256) {
        int r = i / (C / 4), c4 = i % (C / 4);
        size_t off = (size_t)(blockRow + r) * C + c4 * 4;
        float4 nv = *(const float4*)(d_num + off);
        float4 dv = *(const float4*)(d_den + off);
        uint32_t* dst = as_ + r * XSTR + c4 * 4;
        dst[0] = f2tf32(nv.x / fmaxf(dv.x, 1e-9f));
        dst[1] = f2tf32(nv.y / fmaxf(dv.y, 1e-9f));
        dst[2] = f2tf32(nv.z / fmaxf(dv.z, 1e-9f));
        dst[3] = f2tf32(nv.w / fmaxf(dv.w, 1e-9f));
    }

    float acc[12][4];
    #pragma unroll
    for (int a = 0; a < 12; a++)
        #pragma unroll
        for (int b = 0; b < 4; b++) acc[a][b] = 0.0f;

    for (int kc = 0; kc < 12; ++kc) {
        __syncthreads();
        // stage h_w chunk [384 x 32]
        for (int i = tid; i < 384 * 8; i += 256) {
            int n = i >> 3, kk4 = (i & 7) * 4;
            float4 v = *(const float4*)(h_w + (size_t)n * C + kc * 32 + kk4);
            uint32_t* dst = whs + n * WSTR + kk4;
            dst[0] = f2tf32(v.x); dst[1] = f2tf32(v.y); dst[2] = f2tf32(v.z); dst[3] = f2tf32(v.w);
        }
        __syncthreads();
        #pragma unroll
        for (int kk = 0; kk < 4; ++kk) {
            const int krow = kc * 32 + kk * 8;
            int r0 = wm * 16 + p;
            uint32_t a0 = as_[r0 * XSTR + krow + q];
            uint32_t a1 = as_[(r0 + 8) * XSTR + krow + q];
            uint32_t a2 = as_[r0 * XSTR + krow + q + 4];
            uint32_t a3 = as_[(r0 + 8) * XSTR + krow + q + 4];
            #pragma unroll
            for (int nt = 0; nt < 12; ++nt) {
                int nb = wn * 96 + nt * 8 + p;
                uint32_t b0 = whs[nb * WSTR + kk * 8 + q];
                uint32_t b1 = whs[nb * WSTR + kk * 8 + q + 4];
                mma8(acc[nt][0], acc[nt][1], acc[nt][2], acc[nt][3], a0, a1, a2, a3, b0, b1);
            }
        }
    }

    int s0 = blockRow + wm * 16 + p;
    int s1 = s0 + 8;
    #pragma unroll
    for (int nt = 0; nt < 12; ++nt) {
        int col = wn * 96 + nt * 8 + q * 2;
        float hb0 = __ldg(h_b + col), hb1 = __ldg(h_b + col + 1);
        *(float2*)(d_z + (size_t)s0 * C + col) = make_float2(acc[nt][0] + hb0, acc[nt][1] + hb1);
        *(float2*)(d_z + (size_t)s1 * C + col) = make_float2(acc[nt][2] + hb0, acc[nt][3] + hb1);
    }
}

// ---------------------------------------------------------------------------
// Kernel 3: scatter y[h,:] = z[ix[h],:]
// ---------------------------------------------------------------------------
__global__ __launch_bounds__(256) void scatter_kernel(
    const void* __restrict__ ix, float* __restrict__ y) {
    __shared__ int segs[32];
    int tid = threadIdx.x;
    int base = blockIdx.x * 32;
    const int is64 = d_is64;
    if (tid < 32) segs[tid] = seg_at(ix, base + tid, is64);
    __syncthreads();
    for (int i = tid; i < 32 * 96; i += 256) {
        int r = i / 96, c4 = i % 96;
        float4 v = *(const float4*)(d_z + (size_t)segs[r] * C + c4 * 4);
        *(float4*)(y + ((size_t)(base + r)) * C + c4 * 4) = v;
    }
}

// ---------------------------------------------------------------------------
extern "C" void kernel_launch(void* const* d_in, const int* in_sizes, int n_in,
                              void* d_out, int out_size) {
    const float* x   = (const float*)d_in[0];
    const void*  ix  = d_in[1];
    const float* f_w = (const float*)d_in[2];
    const float* f_b = (const float*)d_in[3];
    const float* g_w = (const float*)d_in[4];
    const float* g_b = (const float*)d_in[5];
    const float* h_w = (const float*)d_in[6];
    const float* h_b = (const float*)d_in[7];
    float* y = (float*)d_out;

    cudaFuncSetAttribute(fused_fg_kernel, cudaFuncAttributeMaxDynamicSharedMemorySize, SMEM_MAIN);
    cudaFuncSetAttribute(hgemm_kernel, cudaFuncAttributeMaxDynamicSharedMemorySize, SMEM_H);

    detect_kernel<<<1, 256>>>(ix);
    zero_kernel<<<(S * C + 255) / 256, 256>>>();
    fused_fg_kernel<<<H / BM, 256, SMEM_MAIN>>>(x, ix, f_w, f_b, g_w, g_b);
    hgemm_kernel<<<S / HBM, 256, SMEM_H>>>(h_w, h_b);
    scatter_kernel<<<H / 32, 256>>>(ix, y);
}

// round 4
// speedup vs baseline: 1.6089x; 1.6089x over previous
#include <cuda_runtime.h>
#include <cuda_fp16.h>
#include <cstdint>

#define H 65536
#define C 384
#define S 1024

// scratch (allocation-free rule: device globals)
__device__ float d_num[S * C];
__device__ float d_den[S * C];
__device__ float d_z[S * C];
__device__ int   d_is64;

__device__ __forceinline__ uint32_t f2tf32(float f) {
    uint32_t r;
    asm("cvt.rna.tf32.f32 %0, %1;" : "=r"(r) : "f"(f));
    return r;
}

__device__ __forceinline__ uint32_t pack_h2(float a, float b) {
    __half2 h = __floats2half2_rn(a, b);
    return *(uint32_t*)&h;
}

// fp16 mma m16n8k16, fp32 accum
__device__ __forceinline__ void mma16(float& c0, float& c1, float& c2, float& c3,
                                      uint32_t a0, uint32_t a1, uint32_t a2, uint32_t a3,
                                      uint32_t b0, uint32_t b1) {
    asm volatile(
        "mma.sync.aligned.m16n8k16.row.col.f32.f16.f16.f32 "
        "{%0,%1,%2,%3}, {%4,%5,%6,%7}, {%8,%9}, {%0,%1,%2,%3};\n"
        : "+f"(c0), "+f"(c1), "+f"(c2), "+f"(c3)
        : "r"(a0), "r"(a1), "r"(a2), "r"(a3), "r"(b0), "r"(b1));
}

// tf32 mma for the small hgemm
__device__ __forceinline__ void mma8(float& c0, float& c1, float& c2, float& c3,
                                     uint32_t a0, uint32_t a1, uint32_t a2, uint32_t a3,
                                     uint32_t b0, uint32_t b1) {
    asm volatile(
        "mma.sync.aligned.m16n8k8.row.col.f32.tf32.tf32.f32 "
        "{%0,%1,%2,%3}, {%4,%5,%6,%7}, {%8,%9}, {%0,%1,%2,%3};\n"
        : "+f"(c0), "+f"(c1), "+f"(c2), "+f"(c3)
        : "r"(a0), "r"(a1), "r"(a2), "r"(a3), "r"(b0), "r"(b1));
}

__device__ __forceinline__ void red2(float* p, float a, float b) {
    asm volatile("red.global.add.v2.f32 [%0], {%1,%2};" :: "l"(p), "f"(a), "f"(b) : "memory");
}

__device__ __forceinline__ float clamp50(float v) {
    return fminf(fmaxf(v, -50.0f), 50.0f);
}

__device__ __forceinline__ int seg_at(const void* ix, int i, int is64) {
    int v = is64 ? (int)((const long long*)ix)[i] : ((const int*)ix)[i];
    return min(max(v, 0), S - 1);
}

// ---------------------------------------------------------------------------
// Kernel -1: detect ix dtype (int64 vs int32 reinterpretation)
// ---------------------------------------------------------------------------
__global__ void detect_kernel(const void* ix) {
    __shared__ int bad;
    if (threadIdx.x == 0) bad = 0;
    __syncthreads();
    const long long* p = (const long long*)ix;
    int local = 0;
    for (int i = threadIdx.x; i < 32768; i += blockDim.x) {
        long long v = p[i];
        if (v < 0 || v >= S) local = 1;
    }
    if (local) bad = 1;
    __syncthreads();
    if (threadIdx.x == 0) d_is64 = bad ? 0 : 1;
}

// ---------------------------------------------------------------------------
// Kernel 0: zero num/den
// ---------------------------------------------------------------------------
__global__ void zero_kernel() {
    int i = blockIdx.x * blockDim.x + threadIdx.x;
    if (i < S * C) { d_num[i] = 0.0f; d_den[i] = 0.0f; }
}

// ---------------------------------------------------------------------------
// Kernel 1: fused fx/gx GEMMs (fp16 mma, fp32 accum) + exp + segment red.
// CTA: 128 rows x full K=384 (half) in smem. 6 np-tiles of 64 f-cols + 64
// g-cols; K chunks of 32 with register prefetch. 8 warps: grid 4(M) x 2(N),
// warp tile 32x32 per matrix.
// All smem indices in 32-bit words. x row stride 196 words (192 + 4 pad);
// B row stride 20 words (16 + 4 pad). Both conflict-free for frag LDS.
// ---------------------------------------------------------------------------
#define BM 128
#define XSTRH 196
#define WSTRH 20

#define XS_W     (BM * XSTRH)            // 25088
#define WF_W     XS_W
#define WG_W     (WF_W + 64 * WSTRH)     // +1280
#define SEGS_W   (WG_W + 64 * WSTRH)     // +1280
#define SMEM_FG  ((SEGS_W + BM) * 4)     // 111104 bytes

__global__ __launch_bounds__(256, 2) void fused_fg_kernel(
    const float* __restrict__ x, const void* __restrict__ ix,
    const float* __restrict__ f_w, const float* __restrict__ f_b,
    const float* __restrict__ g_w, const float* __restrict__ g_b) {
    extern __shared__ uint32_t sm[];
    uint32_t* xs  = sm;
    uint32_t* wfs = sm + WF_W;
    uint32_t* wgs = sm + WG_W;
    int*      segs = (int*)(sm + SEGS_W);

    const int tid = threadIdx.x;
    const int lane = tid & 31;
    const int warp = tid >> 5;
    const int wm = warp >> 1;   // 0..3
    const int wn = warp & 1;    // 0..1
    const int q = lane & 3;     // 0..3
    const int p = lane >> 2;    // 0..7
    const int blockRow = blockIdx.x * BM;

    const int is64 = d_is64;
    if (tid < BM) segs[tid] = seg_at(ix, blockRow + tid, is64);

    // load x tile [128 x 384] -> half2 smem
    for (int i = tid; i < BM * (C / 4); i += 256) {
        int r = i / (C / 4), c4 = i % (C / 4);
        float4 v = *(const float4*)(x + (size_t)(blockRow + r) * C + c4 * 4);
        uint32_t* dst = xs + r * XSTRH + c4 * 2;
        dst[0] = pack_h2(v.x, v.y);
        dst[1] = pack_h2(v.z, v.w);
    }

    const int n0 = tid >> 3;        // 0..31
    const int k4 = (tid & 7) * 4;   // 0,4,..,28 (half/float index within chunk)

    for (int np = 0; np < 6; ++np) {
        float accf[2][4][4];
        float accg[2][4][4];
        #pragma unroll
        for (int a = 0; a < 2; a++)
            #pragma unroll
            for (int b = 0; b < 4; b++)
                #pragma unroll
                for (int c = 0; c < 4; c++) { accf[a][b][c] = 0.0f; accg[a][b][c] = 0.0f; }

        const float* fW = f_w + (size_t)(np * 64) * C;
        const float* gW = g_w + (size_t)(np * 64) * C;

        // register prefetch of weight chunk 0
        float4 rf0 = *(const float4*)(fW + (size_t)n0 * C + k4);
        float4 rf1 = *(const float4*)(fW + (size_t)(n0 + 32) * C + k4);
        float4 rg0 = *(const float4*)(gW + (size_t)n0 * C + k4);
        float4 rg1 = *(const float4*)(gW + (size_t)(n0 + 32) * C + k4);

        for (int kc = 0; kc < 12; ++kc) {
            __syncthreads();  // previous chunk fully consumed (and xs/segs ready)
            {
                uint32_t* d0 = wfs + n0 * WSTRH + (k4 >> 1);
                d0[0] = pack_h2(rf0.x, rf0.y); d0[1] = pack_h2(rf0.z, rf0.w);
                uint32_t* d1 = wfs + (n0 + 32) * WSTRH + (k4 >> 1);
                d1[0] = pack_h2(rf1.x, rf1.y); d1[1] = pack_h2(rf1.z, rf1.w);
                uint32_t* e0 = wgs + n0 * WSTRH + (k4 >> 1);
                e0[0] = pack_h2(rg0.x, rg0.y); e0[1] = pack_h2(rg0.z, rg0.w);
                uint32_t* e1 = wgs + (n0 + 32) * WSTRH + (k4 >> 1);
                e1[0] = pack_h2(rg1.x, rg1.y); e1[1] = pack_h2(rg1.z, rg1.w);
            }
            __syncthreads();
            if (kc + 1 < 12) {  // prefetch next chunk while computing
                int ko = (kc + 1) * 32 + k4;
                rf0 = *(const float4*)(fW + (size_t)n0 * C + ko);
                rf1 = *(const float4*)(fW + (size_t)(n0 + 32) * C + ko);
                rg0 = *(const float4*)(gW + (size_t)n0 * C + ko);
                rg1 = *(const float4*)(gW + (size_t)(n0 + 32) * C + ko);
            }
            #pragma unroll
            for (int kk = 0; kk < 2; ++kk) {
                // word offsets: chunk kc spans words [kc*16, kc*16+16); step kk covers 8
                const int kw = kc * 16 + kk * 8;
                uint32_t a[2][4];
                #pragma unroll
                for (int mt = 0; mt < 2; ++mt) {
                    int r0 = wm * 32 + mt * 16 + p;
                    a[mt][0] = xs[r0 * XSTRH + kw + q];
                    a[mt][1] = xs[(r0 + 8) * XSTRH + kw + q];
                    a[mt][2] = xs[r0 * XSTRH + kw + q + 4];
                    a[mt][3] = xs[(r0 + 8) * XSTRH + kw + q + 4];
                }
                #pragma unroll
                for (int nt = 0; nt < 4; ++nt) {
                    int nb = wn * 32 + nt * 8 + p;
                    uint32_t bf0 = wfs[nb * WSTRH + kk * 8 + q];
                    uint32_t bf1 = wfs[nb * WSTRH + kk * 8 + q + 4];
                    uint32_t bg0 = wgs[nb * WSTRH + kk * 8 + q];
                    uint32_t bg1 = wgs[nb * WSTRH + kk * 8 + q + 4];
                    #pragma unroll
                    for (int mt = 0; mt < 2; ++mt) {
                        mma16(accf[mt][nt][0], accf[mt][nt][1], accf[mt][nt][2], accf[mt][nt][3],
                              a[mt][0], a[mt][1], a[mt][2], a[mt][3], bf0, bf1);
                        mma16(accg[mt][nt][0], accg[mt][nt][1], accg[mt][nt][2], accg[mt][nt][3],
                              a[mt][0], a[mt][1], a[mt][2], a[mt][3], bg0, bg1);
                    }
                }
            }
        }

        // epilogue: w = exp(clip(gx+gb)), p = (fx+fb)*w, red into segments
        #pragma unroll
        for (int mt = 0; mt < 2; ++mt) {
            int rloc = wm * 32 + mt * 16 + p;
            int s0 = segs[rloc];
            int s1 = segs[rloc + 8];
            #pragma unroll
            for (int nt = 0; nt < 4; ++nt) {
                int col = np * 64 + wn * 32 + nt * 8 + q * 2;
                float fb0 = __ldg(f_b + col), fb1 = __ldg(f_b + col + 1);
                float gb0 = __ldg(g_b + col), gb1 = __ldg(g_b + col + 1);
                float w00 = __expf(clamp50(accg[mt][nt][0] + gb0));
                float w01 = __expf(clamp50(accg[mt][nt][1] + gb1));
                float w10 = __expf(clamp50(accg[mt][nt][2] + gb0));
                float w11 = __expf(clamp50(accg[mt][nt][3] + gb1));
                float p00 = (accf[mt][nt][0] + fb0) * w00;
                float p01 = (accf[mt][nt][1] + fb1) * w01;
                float p10 = (accf[mt][nt][2] + fb0) * w10;
                float p11 = (accf[mt][nt][3] + fb1) * w11;
                red2(d_num + (size_t)s0 * C + col, p00, p01);
                red2(d_den + (size_t)s0 * C + col, w00, w01);
                red2(d_num + (size_t)s1 * C + col, p10, p11);
                red2(d_den + (size_t)s1 * C + col, w10, w11);
            }
        }
    }
}

// ---------------------------------------------------------------------------
// Kernel 2: z = (num/max(den,1e-9)) @ h_w^T + h_b, 1024 seg rows (tf32)
// grid 128: 32 M-tiles (32 rows) x 4 N-slices (96 cols).
// 8 warps: 2(M) x 4(N); warp = 16 rows x 24 cols (3 n-tiles of 8).
// ---------------------------------------------------------------------------
#define XSTR 388
#define WSTR 36
#define HBM 32
#define HWH_W   (HBM * XSTR)            // 12416
#define SMEM_H  ((HWH_W + 96 * WSTR) * 4)

__global__ __launch_bounds__(256, 1) void hgemm_kernel(
    const float* __restrict__ h_w, const float* __restrict__ h_b) {
    extern __shared__ uint32_t sm[];
    uint32_t* as_ = sm;
    uint32_t* whs = sm + HWH_W;

    const int tid = threadIdx.x;
    const int lane = tid & 31;
    const int warp = tid >> 5;
    const int wm = warp >> 2;   // 0..1
    const int wn = warp & 3;    // 0..3
    const int q = lane & 3;
    const int p = lane >> 2;
    const int blockRow = (blockIdx.x >> 2) * HBM;
    const int ns = blockIdx.x & 3;       // N slice: cols [ns*96, +96)

    for (int i = tid; i < HBM * (C / 4); i += 256) {
        int r = i / (C / 4), c4 = i % (C / 4);
        size_t off = (size_t)(blockRow + r) * C + c4 * 4;
        float4 nv = *(const float4*)(d_num + off);
        float4 dv = *(const float4*)(d_den + off);
        uint32_t* dst = as_ + r * XSTR + c4 * 4;
        dst[0] = f2tf32(nv.x / fmaxf(dv.x, 1e-9f));
        dst[1] = f2tf32(nv.y / fmaxf(dv.y, 1e-9f));
        dst[2] = f2tf32(nv.z / fmaxf(dv.z, 1e-9f));
        dst[3] = f2tf32(nv.w / fmaxf(dv.w, 1e-9f));
    }

    float acc[3][4];
    #pragma unroll
    for (int a = 0; a < 3; a++)
        #pragma unroll
        for (int b = 0; b < 4; b++) acc[a][b] = 0.0f;

    for (int kc = 0; kc < 12; ++kc) {
        __syncthreads();
        for (int i = tid; i < 96 * 8; i += 256) {
            int n = i >> 3, kk4 = (i & 7) * 4;
            float4 v = *(const float4*)(h_w + (size_t)(ns * 96 + n) * C + kc * 32 + kk4);
            uint32_t* dst = whs + n * WSTR + kk4;
            dst[0] = f2tf32(v.x); dst[1] = f2tf32(v.y); dst[2] = f2tf32(v.z); dst[3] = f2tf32(v.w);
        }
        __syncthreads();
        #pragma unroll
        for (int kk = 0; kk < 4; ++kk) {
            const int krow = kc * 32 + kk * 8;
            int r0 = wm * 16 + p;
            uint32_t a0 = as_[r0 * XSTR + krow + q];
            uint32_t a1 = as_[(r0 + 8) * XSTR + krow + q];
            uint32_t a2 = as_[r0 * XSTR + krow + q + 4];
            uint32_t a3 = as_[(r0 + 8) * XSTR + krow + q + 4];
            #pragma unroll
            for (int nt = 0; nt < 3; ++nt) {
                int nb = wn * 24 + nt * 8 + p;
                uint32_t b0 = whs[nb * WSTR + kk * 8 + q];
                uint32_t b1 = whs[nb * WSTR + kk * 8 + q + 4];
                mma8(acc[nt][0], acc[nt][1], acc[nt][2], acc[nt][3], a0, a1, a2, a3, b0, b1);
            }
        }
    }

    int s0 = blockRow + wm * 16 + p;
    int s1 = s0 + 8;
    #pragma unroll
    for (int nt = 0; nt < 3; ++nt) {
        int col = ns * 96 + wn * 24 + nt * 8 + q * 2;
        float hb0 = __ldg(h_b + col), hb1 = __ldg(h_b + col + 1);
        *(float2*)(d_z + (size_t)s0 * C + col) = make_float2(acc[nt][0] + hb0, acc[nt][1] + hb1);
        *(float2*)(d_z + (size_t)s1 * C + col) = make_float2(acc[nt][2] + hb0, acc[nt][3] + hb1);
    }
}

// ---------------------------------------------------------------------------
// Kernel 3: scatter y[h,:] = z[ix[h],:]
// ---------------------------------------------------------------------------
__global__ __launch_bounds__(256) void scatter_kernel(
    const void* __restrict__ ix, float* __restrict__ y) {
    __shared__ int segs[32];
    int tid = threadIdx.x;
    int base = blockIdx.x * 32;
    const int is64 = d_is64;
    if (tid < 32) segs[tid] = seg_at(ix, base + tid, is64);
    __syncthreads();
    for (int i = tid; i < 32 * 96; i += 256) {
        int r = i / 96, c4 = i % 96;
        float4 v = *(const float4*)(d_z + (size_t)segs[r] * C + c4 * 4);
        *(float4*)(y + ((size_t)(base + r)) * C + c4 * 4) = v;
    }
}

// ---------------------------------------------------------------------------
extern "C" void kernel_launch(void* const* d_in, const int* in_sizes, int n_in,
                              void* d_out, int out_size) {
    const float* x   = (const float*)d_in[0];
    const void*  ix  = d_in[1];
    const float* f_w = (const float*)d_in[2];
    const float* f_b = (const float*)d_in[3];
    const float* g_w = (const float*)d_in[4];
    const float* g_b = (const float*)d_in[5];
    const float* h_w = (const float*)d_in[6];
    const float* h_b = (const float*)d_in[7];
    float* y = (float*)d_out;

    cudaFuncSetAttribute(fused_fg_kernel, cudaFuncAttributeMaxDynamicSharedMemorySize, SMEM_FG);
    cudaFuncSetAttribute(hgemm_kernel, cudaFuncAttributeMaxDynamicSharedMemorySize, SMEM_H);

    detect_kernel<<<1, 256>>>(ix);
    zero_kernel<<<(S * C + 255) / 256, 256>>>();
    fused_fg_kernel<<<H / BM, 256, SMEM_FG>>>(x, ix, f_w, f_b, g_w, g_b);
    hgemm_kernel<<<128, 256, SMEM_H>>>(h_w, h_b);
    scatter_kernel<<<H / 32, 256>>>(ix, y);
}

// round 5
// speedup vs baseline: 1.7271x; 1.0735x over previous
#include <cuda_runtime.h>
#include <cuda_fp16.h>
#include <cstdint>

#define H 65536
#define C 384
#define S 1024

// scratch (allocation-free rule: device globals)
// d_acc layout: [S][C][2] = interleaved (num, den) per (segment, col)
__device__ float d_acc[S * C * 2];
__device__ float d_z[S * C];
__device__ int   d_is64;

__device__ __forceinline__ uint32_t f2tf32(float f) {
    uint32_t r;
    asm("cvt.rna.tf32.f32 %0, %1;" : "=r"(r) : "f"(f));
    return r;
}

__device__ __forceinline__ uint32_t pack_h2(float a, float b) {
    __half2 h = __floats2half2_rn(a, b);
    return *(uint32_t*)&h;
}

// fp16 mma m16n8k16, fp32 accum
__device__ __forceinline__ void mma16(float& c0, float& c1, float& c2, float& c3,
                                      uint32_t a0, uint32_t a1, uint32_t a2, uint32_t a3,
                                      uint32_t b0, uint32_t b1) {
    asm volatile(
        "mma.sync.aligned.m16n8k16.row.col.f32.f16.f16.f32 "
        "{%0,%1,%2,%3}, {%4,%5,%6,%7}, {%8,%9}, {%0,%1,%2,%3};\n"
        : "+f"(c0), "+f"(c1), "+f"(c2), "+f"(c3)
        : "r"(a0), "r"(a1), "r"(a2), "r"(a3), "r"(b0), "r"(b1));
}

// tf32 mma for the small hgemm
__device__ __forceinline__ void mma8(float& c0, float& c1, float& c2, float& c3,
                                     uint32_t a0, uint32_t a1, uint32_t a2, uint32_t a3,
                                     uint32_t b0, uint32_t b1) {
    asm volatile(
        "mma.sync.aligned.m16n8k8.row.col.f32.tf32.tf32.f32 "
        "{%0,%1,%2,%3}, {%4,%5,%6,%7}, {%8,%9}, {%0,%1,%2,%3};\n"
        : "+f"(c0), "+f"(c1), "+f"(c2), "+f"(c3)
        : "r"(a0), "r"(a1), "r"(a2), "r"(a3), "r"(b0), "r"(b1));
}

__device__ __forceinline__ void red4(float* p, float a, float b, float c, float d) {
    asm volatile("red.global.add.v4.f32 [%0], {%1,%2,%3,%4};"
                 :: "l"(p), "f"(a), "f"(b), "f"(c), "f"(d) : "memory");
}

__device__ __forceinline__ float clamp50(float v) {
    return fminf(fmaxf(v, -50.0f), 50.0f);
}

__device__ __forceinline__ int seg_at(const void* ix, int i, int is64) {
    int v = is64 ? (int)((const long long*)ix)[i] : ((const int*)ix)[i];
    return min(max(v, 0), S - 1);
}

// ---------------------------------------------------------------------------
// Kernel -1: detect ix dtype (int64 vs int32 reinterpretation)
// ---------------------------------------------------------------------------
__global__ void detect_kernel(const void* ix) {
    __shared__ int bad;
    if (threadIdx.x == 0) bad = 0;
    __syncthreads();
    const long long* p = (const long long*)ix;
    int local = 0;
    for (int i = threadIdx.x; i < 32768; i += blockDim.x) {
        long long v = p[i];
        if (v < 0 || v >= S) local = 1;
    }
    if (local) bad = 1;
    __syncthreads();
    if (threadIdx.x == 0) d_is64 = bad ? 0 : 1;
}

// ---------------------------------------------------------------------------
// Kernel 0: zero accumulator
// ---------------------------------------------------------------------------
__global__ void zero_kernel() {
    int i = blockIdx.x * blockDim.x + threadIdx.x;
    if (i < S * C * 2) d_acc[i] = 0.0f;
}

// ---------------------------------------------------------------------------
// Kernel 1: fused fx/gx GEMMs (fp16 mma, fp32 accum) + exp + segment red.
// CTA: 256 rows x full K=384 (half) in smem; 512 threads = 16 warps,
// warp grid 8(M) x 2(N), warp tile 32x32 per matrix. 6 np-tiles of
// 64 f-cols + 64 g-cols; K chunks of 32 with register prefetch.
// Epilogue: one red.global.add.v4 per (2-col group): {num,den,num,den}.
// ---------------------------------------------------------------------------
#define BM 256
#define XSTRH 196
#define WSTRH 20

#define XS_W     (BM * XSTRH)            // 50176
#define WF_W     XS_W
#define WG_W     (WF_W + 64 * WSTRH)     // +1280
#define SEGS_W   (WG_W + 64 * WSTRH)     // +1280
#define SMEM_FG  ((SEGS_W + BM) * 4)     // 211968 bytes

__global__ __launch_bounds__(512, 1) void fused_fg_kernel(
    const float* __restrict__ x, const void* __restrict__ ix,
    const float* __restrict__ f_w, const float* __restrict__ f_b,
    const float* __restrict__ g_w, const float* __restrict__ g_b) {
    extern __shared__ uint32_t sm[];
    uint32_t* xs  = sm;
    uint32_t* wfs = sm + WF_W;
    uint32_t* wgs = sm + WG_W;
    int*      segs = (int*)(sm + SEGS_W);

    const int tid = threadIdx.x;
    const int lane = tid & 31;
    const int warp = tid >> 5;
    const int wm = warp >> 1;   // 0..7
    const int wn = warp & 1;    // 0..1
    const int q = lane & 3;     // 0..3
    const int p = lane >> 2;    // 0..7
    const int blockRow = blockIdx.x * BM;

    const int is64 = d_is64;
    if (tid < BM) segs[tid] = seg_at(ix, blockRow + tid, is64);

    // load x tile [256 x 384] -> half2 smem
    for (int i = tid; i < BM * (C / 4); i += 512) {
        int r = i / (C / 4), c4 = i % (C / 4);
        float4 v = *(const float4*)(x + (size_t)(blockRow + r) * C + c4 * 4);
        uint32_t* dst = xs + r * XSTRH + c4 * 2;
        dst[0] = pack_h2(v.x, v.y);
        dst[1] = pack_h2(v.z, v.w);
    }

    const int wrow = tid >> 3;      // 0..63 weight row within np tile
    const int k4 = (tid & 7) * 4;   // 0,4,..,28

    for (int np = 0; np < 6; ++np) {
        float accf[2][4][4];
        float accg[2][4][4];
        #pragma unroll
        for (int a = 0; a < 2; a++)
            #pragma unroll
            for (int b = 0; b < 4; b++)
                #pragma unroll
                for (int c = 0; c < 4; c++) { accf[a][b][c] = 0.0f; accg[a][b][c] = 0.0f; }

        const float* fW = f_w + (size_t)(np * 64) * C;
        const float* gW = g_w + (size_t)(np * 64) * C;

        // register prefetch of weight chunk 0
        float4 rf = *(const float4*)(fW + (size_t)wrow * C + k4);
        float4 rg = *(const float4*)(gW + (size_t)wrow * C + k4);

        for (int kc = 0; kc < 12; ++kc) {
            __syncthreads();  // previous chunk fully consumed (and xs/segs ready)
            {
                uint32_t* d0 = wfs + wrow * WSTRH + (k4 >> 1);
                d0[0] = pack_h2(rf.x, rf.y); d0[1] = pack_h2(rf.z, rf.w);
                uint32_t* e0 = wgs + wrow * WSTRH + (k4 >> 1);
                e0[0] = pack_h2(rg.x, rg.y); e0[1] = pack_h2(rg.z, rg.w);
            }
            __syncthreads();
            if (kc + 1 < 12) {  // prefetch next chunk while computing
                int ko = (kc + 1) * 32 + k4;
                rf = *(const float4*)(fW + (size_t)wrow * C + ko);
                rg = *(const float4*)(gW + (size_t)wrow * C + ko);
            }
            #pragma unroll
            for (int kk = 0; kk < 2; ++kk) {
                const int kw = kc * 16 + kk * 8;   // word offset within x row
                uint32_t a[2][4];
                #pragma unroll
                for (int mt = 0; mt < 2; ++mt) {
                    int r0 = wm * 32 + mt * 16 + p;
                    a[mt][0] = xs[r0 * XSTRH + kw + q];
                    a[mt][1] = xs[(r0 + 8) * XSTRH + kw + q];
                    a[mt][2] = xs[r0 * XSTRH + kw + q + 4];
                    a[mt][3] = xs[(r0 + 8) * XSTRH + kw + q + 4];
                }
                #pragma unroll
                for (int nt = 0; nt < 4; ++nt) {
                    int nb = wn * 32 + nt * 8 + p;
                    uint32_t bf0 = wfs[nb * WSTRH + kk * 8 + q];
                    uint32_t bf1 = wfs[nb * WSTRH + kk * 8 + q + 4];
                    uint32_t bg0 = wgs[nb * WSTRH + kk * 8 + q];
                    uint32_t bg1 = wgs[nb * WSTRH + kk * 8 + q + 4];
                    #pragma unroll
                    for (int mt = 0; mt < 2; ++mt) {
                        mma16(accf[mt][nt][0], accf[mt][nt][1], accf[mt][nt][2], accf[mt][nt][3],
                              a[mt][0], a[mt][1], a[mt][2], a[mt][3], bf0, bf1);
                        mma16(accg[mt][nt][0], accg[mt][nt][1], accg[mt][nt][2], accg[mt][nt][3],
                              a[mt][0], a[mt][1], a[mt][2], a[mt][3], bg0, bg1);
                    }
                }
            }
        }

        // epilogue: w = exp(clip(gx+gb)), p = (fx+fb)*w; one red4 per 2 cols
        #pragma unroll
        for (int mt = 0; mt < 2; ++mt) {
            int rloc = wm * 32 + mt * 16 + p;
            int s0 = segs[rloc];
            int s1 = segs[rloc + 8];
            #pragma unroll
            for (int nt = 0; nt < 4; ++nt) {
                int col = np * 64 + wn * 32 + nt * 8 + q * 2;
                float fb0 = __ldg(f_b + col), fb1 = __ldg(f_b + col + 1);
                float gb0 = __ldg(g_b + col), gb1 = __ldg(g_b + col + 1);
                float w00 = __expf(clamp50(accg[mt][nt][0] + gb0));
                float w01 = __expf(clamp50(accg[mt][nt][1] + gb1));
                float w10 = __expf(clamp50(accg[mt][nt][2] + gb0));
                float w11 = __expf(clamp50(accg[mt][nt][3] + gb1));
                float p00 = (accf[mt][nt][0] + fb0) * w00;
                float p01 = (accf[mt][nt][1] + fb1) * w01;
                float p10 = (accf[mt][nt][2] + fb0) * w10;
                float p11 = (accf[mt][nt][3] + fb1) * w11;
                // layout [s][col][2]: {num(col), den(col), num(col+1), den(col+1)}
                red4(d_acc + (size_t)s0 * (2 * C) + col * 2, p00, w00, p01, w01);
                red4(d_acc + (size_t)s1 * (2 * C) + col * 2, p10, w10, p11, w11);
            }
        }
    }
}

// ---------------------------------------------------------------------------
// Kernel 2: z = (num/max(den,1e-9)) @ h_w^T + h_b, 1024 seg rows (tf32)
// grid 128: 32 M-tiles (32 rows) x 4 N-slices (96 cols). Full K=384
// resident in smem (one load phase, one sync, 48 sync-free mma steps).
// 8 warps: 2(M) x 4(N); warp = 16 rows x 24 cols.
// ---------------------------------------------------------------------------
#define HXS 388
#define HBM 32
#define HWH_W   (HBM * HXS)                  // 12416
#define SMEM_H  ((HWH_W + 96 * HXS) * 4)     // 198656 bytes

__global__ __launch_bounds__(256, 1) void hgemm_kernel(
    const float* __restrict__ h_w, const float* __restrict__ h_b) {
    extern __shared__ uint32_t sm[];
    uint32_t* as_ = sm;
    uint32_t* whs = sm + HWH_W;

    const int tid = threadIdx.x;
    const int lane = tid & 31;
    const int warp = tid >> 5;
    const int wm = warp >> 2;   // 0..1
    const int wn = warp & 3;    // 0..3
    const int q = lane & 3;
    const int p = lane >> 2;
    const int blockRow = (blockIdx.x >> 2) * HBM;
    const int ns = blockIdx.x & 3;       // N slice: cols [ns*96, +96)

    // load ratio tile: 32 rows x 96 groups of 4 cols (2 float4 each)
    for (int i = tid; i < HBM * 96; i += 256) {
        int r = i / 96, c4g = i % 96;
        const float* src = d_acc + (size_t)(blockRow + r) * (2 * C) + c4g * 8;
        float4 v0 = *(const float4*)(src);      // num0,den0,num1,den1
        float4 v1 = *(const float4*)(src + 4);  // num2,den2,num3,den3
        uint32_t* dst = as_ + r * HXS + c4g * 4;
        dst[0] = f2tf32(v0.x / fmaxf(v0.y, 1e-9f));
        dst[1] = f2tf32(v0.z / fmaxf(v0.w, 1e-9f));
        dst[2] = f2tf32(v1.x / fmaxf(v1.y, 1e-9f));
        dst[3] = f2tf32(v1.z / fmaxf(v1.w, 1e-9f));
    }

    // load full h_w slice [96 x 384] (high MLP, single phase)
    for (int i = tid; i < 96 * 96; i += 256) {
        int n = i / 96, c4 = i % 96;
        float4 v = *(const float4*)(h_w + (size_t)(ns * 96 + n) * C + c4 * 4);
        uint32_t* dst = whs + n * HXS + c4 * 4;
        dst[0] = f2tf32(v.x); dst[1] = f2tf32(v.y); dst[2] = f2tf32(v.z); dst[3] = f2tf32(v.w);
    }
    __syncthreads();

    float acc[3][4];
    #pragma unroll
    for (int a = 0; a < 3; a++)
        #pragma unroll
        for (int b = 0; b < 4; b++) acc[a][b] = 0.0f;

    #pragma unroll 4
    for (int ks = 0; ks < 48; ++ks) {
        const int krow = ks * 8;
        int r0 = wm * 16 + p;
        uint32_t a0 = as_[r0 * HXS + krow + q];
        uint32_t a1 = as_[(r0 + 8) * HXS + krow + q];
        uint32_t a2 = as_[r0 * HXS + krow + q + 4];
        uint32_t a3 = as_[(r0 + 8) * HXS + krow + q + 4];
        #pragma unroll
        for (int nt = 0; nt < 3; ++nt) {
            int nb = wn * 24 + nt * 8 + p;
            uint32_t b0 = whs[nb * HXS + krow + q];
            uint32_t b1 = whs[nb * HXS + krow + q + 4];
            mma8(acc[nt][0], acc[nt][1], acc[nt][2], acc[nt][3], a0, a1, a2, a3, b0, b1);
        }
    }

    int s0 = blockRow + wm * 16 + p;
    int s1 = s0 + 8;
    #pragma unroll
    for (int nt = 0; nt < 3; ++nt) {
        int col = ns * 96 + wn * 24 + nt * 8 + q * 2;
        float hb0 = __ldg(h_b + col), hb1 = __ldg(h_b + col + 1);
        *(float2*)(d_z + (size_t)s0 * C + col) = make_float2(acc[nt][0] + hb0, acc[nt][1] + hb1);
        *(float2*)(d_z + (size_t)s1 * C + col) = make_float2(acc[nt][2] + hb0, acc[nt][3] + hb1);
    }
}

// ---------------------------------------------------------------------------
// Kernel 3: scatter y[h,:] = z[ix[h],:]
// ---------------------------------------------------------------------------
__global__ __launch_bounds__(256) void scatter_kernel(
    const void* __restrict__ ix, float* __restrict__ y) {
    __shared__ int segs[32];
    int tid = threadIdx.x;
    int base = blockIdx.x * 32;
    const int is64 = d_is64;
    if (tid < 32) segs[tid] = seg_at(ix, base + tid, is64);
    __syncthreads();
    for (int i = tid; i < 32 * 96; i += 256) {
        int r = i / 96, c4 = i % 96;
        float4 v = *(const float4*)(d_z + (size_t)segs[r] * C + c4 * 4);
        *(float4*)(y + ((size_t)(base + r)) * C + c4 * 4) = v;
    }
}

// ---------------------------------------------------------------------------
extern "C" void kernel_launch(void* const* d_in, const int* in_sizes, int n_in,
                              void* d_out, int out_size) {
    const float* x   = (const float*)d_in[0];
    const void*  ix  = d_in[1];
    const float* f_w = (const float*)d_in[2];
    const float* f_b = (const float*)d_in[3];
    const float* g_w = (const float*)d_in[4];
    const float* g_b = (const float*)d_in[5];
    const float* h_w = (const float*)d_in[6];
    const float* h_b = (const float*)d_in[7];
    float* y = (float*)d_out;

    cudaFuncSetAttribute(fused_fg_kernel, cudaFuncAttributeMaxDynamicSharedMemorySize, SMEM_FG);
    cudaFuncSetAttribute(hgemm_kernel, cudaFuncAttributeMaxDynamicSharedMemorySize, SMEM_H);

    detect_kernel<<<1, 256>>>(ix);
    zero_kernel<<<(2 * S * C + 255) / 256, 256>>>();
    fused_fg_kernel<<<H / BM, 512, SMEM_FG>>>(x, ix, f_w, f_b, g_w, g_b);
    hgemm_kernel<<<128, 256, SMEM_H>>>(h_w, h_b);
    scatter_kernel<<<H / 32, 256>>>(ix, y);
}

// round 6
// speedup vs baseline: 1.8114x; 1.0488x over previous
#include <cuda_runtime.h>
#include <cuda_fp16.h>
#include <cstdint>

#define H 65536
#define C 384
#define S 1024

// scratch: d_acc layout [S][C][2] = interleaved (num, den)
__device__ float d_acc[S * C * 2];
__device__ float d_z[S * C];
__device__ int   d_is64;

__device__ __forceinline__ uint32_t smem_u32(const void* p) {
    uint32_t a;
    asm("{ .reg .u64 t; cvta.to.shared.u64 t, %1; cvt.u32.u64 %0, t; }" : "=r"(a) : "l"(p));
    return a;
}

__device__ __forceinline__ uint32_t pack_h2(float a, float b) {
    __half2 h = __floats2half2_rn(a, b);
    return *(uint32_t*)&h;
}

__device__ __forceinline__ void mma16(float& c0, float& c1, float& c2, float& c3,
                                      uint32_t a0, uint32_t a1, uint32_t a2, uint32_t a3,
                                      uint32_t b0, uint32_t b1) {
    asm volatile(
        "mma.sync.aligned.m16n8k16.row.col.f32.f16.f16.f32 "
        "{%0,%1,%2,%3}, {%4,%5,%6,%7}, {%8,%9}, {%0,%1,%2,%3};\n"
        : "+f"(c0), "+f"(c1), "+f"(c2), "+f"(c3)
        : "r"(a0), "r"(a1), "r"(a2), "r"(a3), "r"(b0), "r"(b1));
}

__device__ __forceinline__ void ldsm4(uint32_t& r0, uint32_t& r1, uint32_t& r2, uint32_t& r3,
                                      uint32_t addr) {
    asm volatile("ldmatrix.sync.aligned.m8n8.x4.shared.b16 {%0,%1,%2,%3}, [%4];"
                 : "=r"(r0), "=r"(r1), "=r"(r2), "=r"(r3) : "r"(addr));
}

__device__ __forceinline__ void red4(float* p, float a, float b, float c, float d) {
    asm volatile("red.global.add.v4.f32 [%0], {%1,%2,%3,%4};"
                 :: "l"(p), "f"(a), "f"(b), "f"(c), "f"(d) : "memory");
}

__device__ __forceinline__ float clamp50(float v) {
    return fminf(fmaxf(v, -50.0f), 50.0f);
}

__device__ __forceinline__ int seg_at(const void* ix, int i, int is64) {
    int v = is64 ? (int)((const long long*)ix)[i] : ((const int*)ix)[i];
    return min(max(v, 0), S - 1);
}

// ---------------------------------------------------------------------------
__global__ void detect_kernel(const void* ix) {
    __shared__ int bad;
    if (threadIdx.x == 0) bad = 0;
    __syncthreads();
    const long long* p = (const long long*)ix;
    int local = 0;
    for (int i = threadIdx.x; i < 32768; i += blockDim.x) {
        long long v = p[i];
        if (v < 0 || v >= S) local = 1;
    }
    if (local) bad = 1;
    __syncthreads();
    if (threadIdx.x == 0) d_is64 = bad ? 0 : 1;
}

__global__ void zero_kernel() {
    int i = blockIdx.x * blockDim.x + threadIdx.x;
    if (i < S * C * 2) d_acc[i] = 0.0f;
}

// ---------------------------------------------------------------------------
// Kernel 1: fused fx/gx GEMMs (fp16 mma, fp32 accum) + exp + segment red.
// CTA: 256 rows x full K=384 (half) resident; 512 threads = 16 warps,
// warp grid 8(M) x 2(N), warp tile 32x32 per matrix. 6 np-tiles of 64
// f-cols + 64 g-cols. K streamed in chunks of 32 with PING-PONG weight
// buffers: stage chunk kc+1 while computing chunk kc; ONE sync per chunk.
// All fragments loaded via ldmatrix.x4 (6 LDSM per kk-step vs 24 LDS).
// Epilogue: red.global.add.v4 {num,den,num,den} per 2 cols.
// ---------------------------------------------------------------------------
#define BM 256
#define XSTRH 196   // x row stride in words (192 + 4 pad)
#define WSTRH 20    // weight row stride in words (16 + 4 pad)

#define XS_W     (BM * XSTRH)            // 50176 words
#define WB_W     2560                    // one ping-pong buffer: f(1280)+g(1280)
#define WBUF_W   XS_W
#define SEGS_W   (XS_W + 2 * WB_W)       // 55296
#define SMEM_FG  ((SEGS_W + BM) * 4)     // 222208 bytes

__global__ __launch_bounds__(512, 1) void fused_fg_kernel(
    const float* __restrict__ x, const void* __restrict__ ix,
    const float* __restrict__ f_w, const float* __restrict__ f_b,
    const float* __restrict__ g_w, const float* __restrict__ g_b) {
    extern __shared__ uint32_t sm[];
    int* segs = (int*)(sm + SEGS_W);
    const uint32_t xsb = smem_u32(sm);

    const int tid = threadIdx.x;
    const int lane = tid & 31;
    const int warp = tid >> 5;
    const int wm = warp >> 1;   // 0..7
    const int wn = warp & 1;    // 0..1
    const int q = lane & 3;
    const int p = lane >> 2;
    const int blockRow = blockIdx.x * BM;

    const int is64 = d_is64;
    if (tid < BM) segs[tid] = seg_at(ix, blockRow + tid, is64);

    // load x tile [256 x 384] -> half2 smem
    for (int i = tid; i < BM * (C / 4); i += 512) {
        int r = i / (C / 4), c4 = i % (C / 4);
        float4 v = *(const float4*)(x + (size_t)(blockRow + r) * C + c4 * 4);
        uint32_t* dst = sm + r * XSTRH + c4 * 2;
        dst[0] = pack_h2(v.x, v.y);
        dst[1] = pack_h2(v.z, v.w);
    }

    // ldmatrix lane-address offsets (bytes)
    const int lm = lane >> 3;      // matrix id 0..3
    const int li = lane & 7;
    // A: matrix m: row = wmBase + mt*16 + (m&1)*8 + i ; colword = (m>>1)*4
    uint32_t aOff0 = (uint32_t)(((wm * 32 + ((lm & 1) << 3) + li) * XSTRH + ((lm >> 1) << 2)) * 4);
    uint32_t aOff1 = aOff0 + (uint32_t)(16 * XSTRH * 4);
    // B: matrix m: row = wn*32 + ntp*16 + (m>>1)*8 + i ; colword = (m&1)*4
    uint32_t bOff0 = (uint32_t)(((wn * 32 + ((lm >> 1) << 3) + li) * WSTRH + ((lm & 1) << 2)) * 4);
    uint32_t bOff1 = bOff0 + (uint32_t)(16 * WSTRH * 4);

    const int wrow = tid >> 3;      // 0..63: weight row within np-tile
    const int kq = tid & 7;         // 8 threads cover 16 words per row

    for (int np = 0; np < 6; ++np) {
        float accf[2][4][4];
        float accg[2][4][4];
        #pragma unroll
        for (int a = 0; a < 2; a++)
            #pragma unroll
            for (int b = 0; b < 4; b++)
                #pragma unroll
                for (int c = 0; c < 4; c++) { accf[a][b][c] = 0.0f; accg[a][b][c] = 0.0f; }

        const float* fW = f_w + (size_t)(np * 64) * C + (size_t)wrow * C + kq * 4;
        const float* gW = g_w + (size_t)(np * 64) * C + (size_t)wrow * C + kq * 4;

        // stage chunk 0 into buffer 0
        {
            float4 rf = *(const float4*)(fW);
            float4 rg = *(const float4*)(gW);
            uint32_t* d0 = sm + WBUF_W + wrow * WSTRH + kq * 2;
            d0[0] = pack_h2(rf.x, rf.y); d0[1] = pack_h2(rf.z, rf.w);
            uint32_t* e0 = d0 + 1280;
            e0[0] = pack_h2(rg.x, rg.y); e0[1] = pack_h2(rg.z, rg.w);
        }
        float4 rf = *(const float4*)(fW + 32);
        float4 rg = *(const float4*)(gW + 32);
        __syncthreads();

        for (int kc = 0; kc < 12; ++kc) {
            const int b = kc & 1;
            // stage chunk kc+1 into the other buffer (read last at kc-1, synced)
            if (kc < 11) {
                uint32_t* d0 = sm + WBUF_W + (b ^ 1) * WB_W + wrow * WSTRH + kq * 2;
                d0[0] = pack_h2(rf.x, rf.y); d0[1] = pack_h2(rf.z, rf.w);
                uint32_t* e0 = d0 + 1280;
                e0[0] = pack_h2(rg.x, rg.y); e0[1] = pack_h2(rg.z, rg.w);
                if (kc < 10) {
                    rf = *(const float4*)(fW + (kc + 2) * 32);
                    rg = *(const float4*)(gW + (kc + 2) * 32);
                }
            }
            // compute from buffer b
            const uint32_t fb = xsb + (WBUF_W + b * WB_W) * 4;
            const uint32_t gb = fb + 1280 * 4;
            const uint32_t aKw = xsb + (uint32_t)(kc * 64);  // kc*16 words
            #pragma unroll
            for (int kk = 0; kk < 2; ++kk) {
                const uint32_t kb = (uint32_t)(kk * 32);
                uint32_t A0[4], A1[4], F0[4], F1[4], G0[4], G1[4];
                ldsm4(A0[0], A0[1], A0[2], A0[3], aKw + aOff0 + kb);
                ldsm4(A1[0], A1[1], A1[2], A1[3], aKw + aOff1 + kb);
                ldsm4(F0[0], F0[1], F0[2], F0[3], fb + bOff0 + kb);
                ldsm4(F1[0], F1[1], F1[2], F1[3], fb + bOff1 + kb);
                ldsm4(G0[0], G0[1], G0[2], G0[3], gb + bOff0 + kb);
                ldsm4(G1[0], G1[1], G1[2], G1[3], gb + bOff1 + kb);
                // F0 = {bf0(nt0), bf1(nt0), bf0(nt1), bf1(nt1)}, F1 = nt2,nt3
                #pragma unroll
                for (int nt = 0; nt < 4; ++nt) {
                    uint32_t bf0 = (nt < 2) ? F0[(nt & 1) * 2]     : F1[(nt & 1) * 2];
                    uint32_t bf1 = (nt < 2) ? F0[(nt & 1) * 2 + 1] : F1[(nt & 1) * 2 + 1];
                    uint32_t bg0 = (nt < 2) ? G0[(nt & 1) * 2]     : G1[(nt & 1) * 2];
                    uint32_t bg1 = (nt < 2) ? G0[(nt & 1) * 2 + 1] : G1[(nt & 1) * 2 + 1];
                    mma16(accf[0][nt][0], accf[0][nt][1], accf[0][nt][2], accf[0][nt][3],
                          A0[0], A0[1], A0[2], A0[3], bf0, bf1);
                    mma16(accg[0][nt][0], accg[0][nt][1], accg[0][nt][2], accg[0][nt][3],
                          A0[0], A0[1], A0[2], A0[3], bg0, bg1);
                    mma16(accf[1][nt][0], accf[1][nt][1], accf[1][nt][2], accf[1][nt][3],
                          A1[0], A1[1], A1[2], A1[3], bf0, bf1);
                    mma16(accg[1][nt][0], accg[1][nt][1], accg[1][nt][2], accg[1][nt][3],
                          A1[0], A1[1], A1[2], A1[3], bg0, bg1);
                }
            }
            __syncthreads();
        }

        // epilogue
        #pragma unroll
        for (int mt = 0; mt < 2; ++mt) {
            int rloc = wm * 32 + mt * 16 + p;
            int s0 = segs[rloc];
            int s1 = segs[rloc + 8];
            #pragma unroll
            for (int nt = 0; nt < 4; ++nt) {
                int col = np * 64 + wn * 32 + nt * 8 + q * 2;
                float fb0 = __ldg(f_b + col), fb1 = __ldg(f_b + col + 1);
                float gb0 = __ldg(g_b + col), gb1 = __ldg(g_b + col + 1);
                float w00 = __expf(clamp50(accg[0][nt][0] + gb0));
                float w01 = __expf(clamp50(accg[0][nt][1] + gb1));
                float w10 = __expf(clamp50(accg[0][nt][2] + gb0));
                float w11 = __expf(clamp50(accg[0][nt][3] + gb1));
                float p00 = (accf[0][nt][0] + fb0) * w00;
                float p01 = (accf[0][nt][1] + fb1) * w01;
                float p10 = (accf[0][nt][2] + fb0) * w10;
                float p11 = (accf[0][nt][3] + fb1) * w11;
                red4(d_acc + (size_t)s0 * (2 * C) + col * 2, p00, w00, p01, w01);
                red4(d_acc + (size_t)s1 * (2 * C) + col * 2, p10, w10, p11, w11);
                // mt=1 accumulators
                int s2 = segs[wm * 32 + 16 + p];
                int s3 = segs[wm * 32 + 16 + p + 8];
                float v00 = __expf(clamp50(accg[1][nt][0] + gb0));
                float v01 = __expf(clamp50(accg[1][nt][1] + gb1));
                float v10 = __expf(clamp50(accg[1][nt][2] + gb0));
                float v11 = __expf(clamp50(accg[1][nt][3] + gb1));
                float q00 = (accf[1][nt][0] + fb0) * v00;
                float q01 = (accf[1][nt][1] + fb1) * v01;
                float q10 = (accf[1][nt][2] + fb0) * v10;
                float q11 = (accf[1][nt][3] + fb1) * v11;
                red4(d_acc + (size_t)s2 * (2 * C) + col * 2, q00, v00, q01, v01);
                red4(d_acc + (size_t)s3 * (2 * C) + col * 2, q10, v10, q11, v11);
            }
            if (mt == 0) break;  // mt=1 handled inline above
        }
    }
}

// ---------------------------------------------------------------------------
// Kernel 2: z = (num/max(den,1e-9)) @ h_w^T + h_b over 1024 seg rows (fp16)
// grid 192 = 32 M-tiles (32 rows) x 6 N-slices (64 cols). Full K resident.
// 8 warps: 2(M) x 4(N); warp = 16 rows x 16 cols (2 n-tiles of 8).
// ---------------------------------------------------------------------------
#define HRS 196
#define SMEM_H ((32 * HRS + 64 * HRS) * 4)   // 75264 bytes

__global__ __launch_bounds__(256, 2) void hgemm_kernel(
    const float* __restrict__ h_w, const float* __restrict__ h_b) {
    extern __shared__ uint32_t sm[];
    uint32_t* as_ = sm;
    uint32_t* whs = sm + 32 * HRS;

    const int tid = threadIdx.x;
    const int lane = tid & 31;
    const int warp = tid >> 5;
    const int wm = warp >> 2;   // 0..1
    const int wn = warp & 3;    // 0..3
    const int q = lane & 3;
    const int p = lane >> 2;
    const int blockRow = (blockIdx.x / 6) * 32;
    const int ns = blockIdx.x % 6;       // cols [ns*64, +64)

    // ratio tile [32 x 384] -> half
    for (int i = tid; i < 32 * 96; i += 256) {
        int r = i / 96, c4g = i % 96;
        const float* src = d_acc + (size_t)(blockRow + r) * (2 * C) + c4g * 8;
        float4 v0 = *(const float4*)(src);
        float4 v1 = *(const float4*)(src + 4);
        uint32_t* dst = as_ + r * HRS + c4g * 2;
        dst[0] = pack_h2(v0.x / fmaxf(v0.y, 1e-9f), v0.z / fmaxf(v0.w, 1e-9f));
        dst[1] = pack_h2(v1.x / fmaxf(v1.y, 1e-9f), v1.z / fmaxf(v1.w, 1e-9f));
    }
    // weight slice [64 x 384] -> half
    for (int i = tid; i < 64 * 96; i += 256) {
        int n = i / 96, c4 = i % 96;
        float4 v = *(const float4*)(h_w + (size_t)(ns * 64 + n) * C + c4 * 4);
        uint32_t* dst = whs + n * HRS + c4 * 2;
        dst[0] = pack_h2(v.x, v.y);
        dst[1] = pack_h2(v.z, v.w);
    }
    __syncthreads();

    float acc[2][4];
    #pragma unroll
    for (int a = 0; a < 2; a++)
        #pragma unroll
        for (int b = 0; b < 4; b++) acc[a][b] = 0.0f;

    const int r0 = wm * 16 + p;
    #pragma unroll 4
    for (int ks = 0; ks < 24; ++ks) {
        const int kw = ks * 8;
        uint32_t a0 = as_[r0 * HRS + kw + q];
        uint32_t a1 = as_[(r0 + 8) * HRS + kw + q];
        uint32_t a2 = as_[r0 * HRS + kw + q + 4];
        uint32_t a3 = as_[(r0 + 8) * HRS + kw + q + 4];
        #pragma unroll
        for (int nt = 0; nt < 2; ++nt) {
            int nb = wn * 16 + nt * 8 + p;
            uint32_t b0 = whs[nb * HRS + kw + q];
            uint32_t b1 = whs[nb * HRS + kw + q + 4];
            mma16(acc[nt][0], acc[nt][1], acc[nt][2], acc[nt][3], a0, a1, a2, a3, b0, b1);
        }
    }

    int s0 = blockRow + wm * 16 + p;
    int s1 = s0 + 8;
    #pragma unroll
    for (int nt = 0; nt < 2; ++nt) {
        int col = ns * 64 + wn * 16 + nt * 8 + q * 2;
        float hb0 = __ldg(h_b + col), hb1 = __ldg(h_b + col + 1);
        *(float2*)(d_z + (size_t)s0 * C + col) = make_float2(acc[nt][0] + hb0, acc[nt][1] + hb1);
        *(float2*)(d_z + (size_t)s1 * C + col) = make_float2(acc[nt][2] + hb0, acc[nt][3] + hb1);
    }
}

// ---------------------------------------------------------------------------
// Kernel 3: scatter y[h,:] = z[ix[h],:]
// ---------------------------------------------------------------------------
__global__ __launch_bounds__(256) void scatter_kernel(
    const void* __restrict__ ix, float* __restrict__ y) {
    __shared__ int segs[32];
    int tid = threadIdx.x;
    int base = blockIdx.x * 32;
    const int is64 = d_is64;
    if (tid < 32) segs[tid] = seg_at(ix, base + tid, is64);
    __syncthreads();
    for (int i = tid; i < 32 * 96; i += 256) {
        int r = i / 96, c4 = i % 96;
        float4 v = *(const float4*)(d_z + (size_t)segs[r] * C + c4 * 4);
        *(float4*)(y + ((size_t)(base + r)) * C + c4 * 4) = v;
    }
}

// ---------------------------------------------------------------------------
extern "C" void kernel_launch(void* const* d_in, const int* in_sizes, int n_in,
                              void* d_out, int out_size) {
    const float* x   = (const float*)d_in[0];
    const void*  ix  = d_in[1];
    const float* f_w = (const float*)d_in[2];
    const float* f_b = (const float*)d_in[3];
    const float* g_w = (const float*)d_in[4];
    const float* g_b = (const float*)d_in[5];
    const float* h_w = (const float*)d_in[6];
    const float* h_b = (const float*)d_in[7];
    float* y = (float*)d_out;

    cudaFuncSetAttribute(fused_fg_kernel, cudaFuncAttributeMaxDynamicSharedMemorySize, SMEM_FG);
    cudaFuncSetAttribute(hgemm_kernel, cudaFuncAttributeMaxDynamicSharedMemorySize, SMEM_H);

    detect_kernel<<<1, 256>>>(ix);
    zero_kernel<<<(2 * S * C + 255) / 256, 256>>>();
    fused_fg_kernel<<<H / BM, 512, SMEM_FG>>>(x, ix, f_w, f_b, g_w, g_b);
    hgemm_kernel<<<192, 256, SMEM_H>>>(h_w, h_b);
    scatter_kernel<<<H / 32, 256>>>(ix, y);
}